// round 13
// baseline (speedup 1.0000x reference)
#include <cuda_runtime.h>
#include <cuda_fp16.h>
#include <cstdint>
#include <cstddef>

#define NN_MAX 100000
#define NE_MAX 1600000
#define DIN 256
#define DH 128
#define CAP 64
#define OVF_MAX 8192

typedef unsigned long long ull;

// ---------------------------------------------------------------- scratch
__device__ __half g_xf[NN_MAX * DH];   // (x @ W_f^T)[n]  fp16, unscaled
__device__ __half g_xb[NN_MAX * DH];   // (x @ W_b^T)[n]  fp16, unscaled
__device__ __half g_wc[256 * DIN];     // W fp16 [n][k] (Wf rows 0-127, Wb 128-255)
__device__ int   g_cnt_c[NN_MAX];      // in-degree (edges only)
__device__ int   g_cnt_r[NN_MAX];      // out-degree (edges only)
__device__ float g_isr_in[NN_MAX];
__device__ float g_isr_out[NN_MAX];
__device__ int   g_bf[NN_MAX * CAP];   // fwd buckets: sources (rows) per col
__device__ int   g_bb[NN_MAX * CAP];   // bwd buckets: sources (cols) per row
__device__ int   g_novf[2];
__device__ int2  g_ovf_f[OVF_MAX];     // (dest c, src r)
__device__ int2  g_ovf_b[OVF_MAX];     // (dest r, src c)
__device__ int   g_is64;

__device__ __forceinline__ int edge_val(const void* ei, size_t idx) {
    if (g_is64) return (int)((const long long*)ei)[idx];
    return ((const int*)ei)[idx];
}

// ---------------------------------------------------------------- dtype detect
__global__ void detect_flag_kernel(const unsigned* __restrict__ w, int nwords) {
    __shared__ unsigned s;
    if (threadIdx.x == 0) s = 0;
    __syncthreads();
    unsigned acc = 0;
    for (int i = threadIdx.x; i < 16384 && 2 * i + 1 < nwords; i += blockDim.x)
        acc |= w[2 * i + 1];
    #pragma unroll
    for (int o = 16; o > 0; o >>= 1)
        acc |= __shfl_xor_sync(0xffffffffu, acc, o);
    if ((threadIdx.x & 31) == 0 && acc) atomicOr(&s, acc);
    __syncthreads();
    if (threadIdx.x == 0) g_is64 = (s == 0u) ? 1 : 0;
}

// ---------------------------------------------------------------- single-pass bucket CSR
__global__ void fill_bucket_kernel(const void* __restrict__ ei, int E) {
    int e = blockIdx.x * blockDim.x + threadIdx.x;
    if (e >= E) return;
    int c = edge_val(ei, e);
    int r = edge_val(ei, (size_t)E + e);
    int pc = atomicAdd(&g_cnt_c[c], 1);
    if (pc < CAP) g_bf[c * CAP + pc] = r;
    else {
        int o = atomicAdd(&g_novf[0], 1);
        if (o < OVF_MAX) g_ovf_f[o] = make_int2(c, r);
    }
    int pr = atomicAdd(&g_cnt_r[r], 1);
    if (pr < CAP) g_bb[r * CAP + pr] = c;
    else {
        int o = atomicAdd(&g_novf[1], 1);
        if (o < OVF_MAX) g_ovf_b[o] = make_int2(r, c);
    }
}

__global__ void isr_kernel(int M) {
    int n = blockIdx.x * blockDim.x + threadIdx.x;
    if (n >= M) return;
    g_isr_in[n]  = rsqrtf((float)(g_cnt_c[n] + 1));
    g_isr_out[n] = rsqrtf((float)(g_cnt_r[n] + 1));
}

// ---------------------------------------------------------------- W prep (fp16)
__global__ void w_conv_kernel(const float* __restrict__ Wf,
                              const float* __restrict__ Wb) {
    int idx = blockIdx.x * blockDim.x + threadIdx.x;
    if (idx >= 256 * 256) return;
    int n = idx >> 8, k = idx & 255;
    float v = (n < DH) ? Wf[n * DIN + k] : Wb[(n - DH) * DIN + k];
    g_wc[n * DIN + k] = __float2half_rn(v);
}

// ---------------------------------------------------------------- HMMA GEMM (reads x fp32 directly)
#define LDA 72
#define LDB 72
#define A_BUF (64 * LDA)
#define B_BUF (256 * LDB)
#define GEMM_SMEM ((2 * A_BUF + 2 * B_BUF) * 2)
#define NCHUNK 4

__device__ __forceinline__ void cp16(unsigned daddr, const void* src, unsigned sz) {
    asm volatile("cp.async.ca.shared.global [%0], [%1], 16, %2;"
                 :: "r"(daddr), "l"(src), "r"(sz) : "memory");
}

__global__ __launch_bounds__(256)
void gemm_hmma_kernel(const float* __restrict__ x, int M)
{
    extern __shared__ __align__(16) __half smem[];
    __half* As = smem;
    __half* Bs = smem + 2 * A_BUF;

    const int t   = threadIdx.x;
    const int wid = t >> 5;
    const int lid = t & 31;
    const int m0  = blockIdx.x * 64;
    const int wm  = (wid & 1) * 32;
    const int wn  = (wid >> 1) * 64;

    float c[2][8][4];
    #pragma unroll
    for (int i = 0; i < 2; ++i)
        #pragma unroll
        for (int j = 0; j < 8; ++j)
            #pragma unroll
            for (int q = 0; q < 4; ++q) c[i][j][q] = 0.f;

    unsigned bs_base = (unsigned)__cvta_generic_to_shared(Bs);

    auto issue_load = [&](int ch) {
        int buf = ch & 1;
        int k0 = ch * 64;
        #pragma unroll
        for (int i = 0; i < 8; ++i) {
            int idx = t + 256 * i;
            int row = idx >> 3, kq = idx & 7;
            const __half* src = g_wc + (size_t)row * DIN + k0 + kq * 8;
            unsigned dst = bs_base + (buf * B_BUF + row * LDB + kq * 8) * 2;
            cp16(dst, src, 16u);
        }
        asm volatile("cp.async.commit_group;" ::: "memory");
        #pragma unroll
        for (int i = 0; i < 2; ++i) {
            int idx = t + 256 * i;
            int row = idx >> 3, kq = idx & 7;
            float4 f0 = make_float4(0.f, 0.f, 0.f, 0.f), f1 = f0;
            if (m0 + row < M) {
                const float* src = x + (size_t)(m0 + row) * DIN + k0 + kq * 8;
                f0 = *(const float4*)src;
                f1 = *(const float4*)(src + 4);
            }
            __half2 h0 = __floats2half2_rn(f0.x, f0.y);
            __half2 h1 = __floats2half2_rn(f0.z, f0.w);
            __half2 h2 = __floats2half2_rn(f1.x, f1.y);
            __half2 h3 = __floats2half2_rn(f1.z, f1.w);
            uint4 u = make_uint4(*(unsigned*)&h0, *(unsigned*)&h1,
                                 *(unsigned*)&h2, *(unsigned*)&h3);
            *(uint4*)(As + buf * A_BUF + row * LDA + kq * 8) = u;
        }
    };

    issue_load(0);
    issue_load(1);

    #pragma unroll 1
    for (int ch = 0; ch < NCHUNK; ++ch) {
        if (ch == NCHUNK - 1) asm volatile("cp.async.wait_group 0;" ::: "memory");
        else                  asm volatile("cp.async.wait_group 1;" ::: "memory");
        __syncthreads();

        const __half* A_ = As + (ch & 1) * A_BUF;
        const __half* B_ = Bs + (ch & 1) * B_BUF;

        #pragma unroll
        for (int k16 = 0; k16 < 4; ++k16) {
            int k0 = k16 * 16 + (lid & 3) * 2;
            unsigned a[2][4];
            #pragma unroll
            for (int mt = 0; mt < 2; ++mt) {
                int r = wm + mt * 16 + (lid >> 2);
                a[mt][0] = *(const unsigned*)(A_ + r * LDA + k0);
                a[mt][1] = *(const unsigned*)(A_ + (r + 8) * LDA + k0);
                a[mt][2] = *(const unsigned*)(A_ + r * LDA + k0 + 8);
                a[mt][3] = *(const unsigned*)(A_ + (r + 8) * LDA + k0 + 8);
            }
            #pragma unroll
            for (int nt = 0; nt < 8; ++nt) {
                int nrow = wn + nt * 8 + (lid >> 2);
                unsigned b0 = *(const unsigned*)(B_ + nrow * LDB + k0);
                unsigned b1 = *(const unsigned*)(B_ + nrow * LDB + k0 + 8);
                #pragma unroll
                for (int mt = 0; mt < 2; ++mt) {
                    asm volatile(
                        "mma.sync.aligned.m16n8k16.row.col.f32.f16.f16.f32 "
                        "{%0,%1,%2,%3}, {%4,%5,%6,%7}, {%8,%9}, {%0,%1,%2,%3};"
                        : "+f"(c[mt][nt][0]), "+f"(c[mt][nt][1]),
                          "+f"(c[mt][nt][2]), "+f"(c[mt][nt][3])
                        : "r"(a[mt][0]), "r"(a[mt][1]), "r"(a[mt][2]), "r"(a[mt][3]),
                          "r"(b0), "r"(b1));
                }
            }
        }
        __syncthreads();
        if (ch + 2 < NCHUNK) issue_load(ch + 2);
    }

    #pragma unroll
    for (int mt = 0; mt < 2; ++mt) {
        #pragma unroll
        for (int half2s = 0; half2s < 2; ++half2s) {
            int node = m0 + wm + mt * 16 + (lid >> 2) + half2s * 8;
            if (node >= M) continue;
            #pragma unroll
            for (int nt = 0; nt < 8; ++nt) {
                int n = wn + nt * 8 + (lid & 3) * 2;
                __half2 h = __floats2half2_rn(c[mt][nt][half2s * 2],
                                              c[mt][nt][half2s * 2 + 1]);
                __half* dst = (n < DH) ? (g_xf + (size_t)node * DH + n)
                                       : (g_xb + (size_t)node * DH + (n - DH));
                *(__half2*)dst = h;
            }
        }
    }
}

// ---------------------------------------------------------------- gather (2 edges/warp-step)
// Warp per (node, sel). Lanes 0-15 process even edges, 16-31 odd edges;
// each half covers all 128 cols via uint4 (8 halves/lane). Final cross-half
// shfl reduction; lanes 0-15 write the y half-row.
__global__ __launch_bounds__(256)
void gather_kernel(int sel, const float* __restrict__ bias,
                   float* __restrict__ y, int M)
{
    int lane = threadIdx.x & 31;
    int l16  = lane & 15;
    int half = lane >> 4;
    int n = (blockIdx.x * blockDim.x + threadIdx.x) >> 5;
    if (n >= M) return;

    const int* elist   = sel ? g_bb : g_bf;
    const int* cnt     = sel ? g_cnt_r : g_cnt_c;
    const __half* feat = sel ? g_xb : g_xf;
    const float* sarr  = sel ? g_isr_in : g_isr_out;
    float nscale = sel ? g_isr_out[n] : g_isr_in[n];

    int beg = n * CAP;
    int deg = min(cnt[n], CAP);

    float acc[8];
    #pragma unroll
    for (int q = 0; q < 8; ++q) acc[q] = 0.f;

    if (half == 0) {   // self term once
        float ws = sarr[n];
        uint4 v = *(const uint4*)(feat + (size_t)n * DH + l16 * 8);
        unsigned vv[4] = {v.x, v.y, v.z, v.w};
        #pragma unroll
        for (int q = 0; q < 4; ++q) {
            float2 f = __half22float2(*(__half2*)&vv[q]);
            acc[2 * q]     = f.x * ws;
            acc[2 * q + 1] = f.y * ws;
        }
    }

    for (int base = 0; base < deg; base += 32) {
        int e = base + lane;
        int src = 0; float w = 0.f;
        if (e < deg) {
            src = __ldg(elist + beg + e);
            w   = __ldg(sarr + src);
        }
        int m = min(32, deg - base);
        int j = 0;
        // batch: 8 edges (4 per half), 4 x LDG.128 in flight per lane
        for (; j + 8 <= m; j += 8) {
            uint4 v[4]; float ww[4];
            #pragma unroll
            for (int u = 0; u < 4; ++u) {
                int idx = j + 2 * u + half;
                int s   = __shfl_sync(0xffffffffu, src, idx);
                ww[u]   = __shfl_sync(0xffffffffu, w, idx);
                v[u]    = __ldg((const uint4*)(feat + (size_t)s * DH) + l16);
            }
            #pragma unroll
            for (int u = 0; u < 4; ++u) {
                unsigned vv[4] = {v[u].x, v[u].y, v[u].z, v[u].w};
                #pragma unroll
                for (int q = 0; q < 4; ++q) {
                    float2 f = __half22float2(*(__half2*)&vv[q]);
                    acc[2 * q]     += f.x * ww[u];
                    acc[2 * q + 1] += f.y * ww[u];
                }
            }
        }
        // remainder: pairs (idx = j + half <= m <= 31, w preloaded 0 when invalid)
        for (; j < m; j += 2) {
            int idx = j + half;
            int s    = __shfl_sync(0xffffffffu, src, idx);
            float ww = __shfl_sync(0xffffffffu, w, idx);
            if (idx >= m) ww = 0.f;
            uint4 v = __ldg((const uint4*)(feat + (size_t)s * DH) + l16);
            unsigned vv[4] = {v.x, v.y, v.z, v.w};
            #pragma unroll
            for (int q = 0; q < 4; ++q) {
                float2 f = __half22float2(*(__half2*)&vv[q]);
                acc[2 * q]     += f.x * ww;
                acc[2 * q + 1] += f.y * ww;
            }
        }
    }

    // cross-half reduction
    #pragma unroll
    for (int q = 0; q < 8; ++q)
        acc[q] += __shfl_down_sync(0xffffffffu, acc[q], 16);

    if (half == 0) {
        const float4* bq = (const float4*)(bias + sel * DH + l16 * 8);
        float4 b0 = bq[0], b1 = bq[1];
        float4 o0 = make_float4(b0.x + nscale * acc[0], b0.y + nscale * acc[1],
                                b0.z + nscale * acc[2], b0.w + nscale * acc[3]);
        float4 o1 = make_float4(b1.x + nscale * acc[4], b1.y + nscale * acc[5],
                                b1.z + nscale * acc[6], b1.w + nscale * acc[7]);
        float4* dst = (float4*)(y + (size_t)n * 256 + sel * DH + l16 * 8);
        dst[0] = o0;
        dst[1] = o1;
    }
}

// ---------------------------------------------------------------- overflow replay (normally empty)
__global__ void ovf_kernel(int sel, float* __restrict__ y) {
    int n_ovf = min(g_novf[sel], OVF_MAX);
    if (n_ovf <= 0) return;
    const int2* lst = sel ? g_ovf_b : g_ovf_f;
    const __half* feat = sel ? g_xb : g_xf;
    int lane = threadIdx.x & 31;
    int wpg = (gridDim.x * blockDim.x) >> 5;
    for (int i = (blockIdx.x * blockDim.x + threadIdx.x) >> 5; i < n_ovf; i += wpg) {
        int2 p = lst[i];   // (dest, src)
        float w = sel ? (g_isr_out[p.x] * g_isr_in[p.y])
                      : (g_isr_in[p.x] * g_isr_out[p.y]);
        uint2 v = *(const uint2*)(feat + (size_t)p.y * DH + lane * 4);
        float2 f0 = __half22float2(*(__half2*)&v.x);
        float2 f1 = __half22float2(*(__half2*)&v.y);
        float* dst = y + (size_t)p.x * 256 + sel * DH + lane * 4;
        atomicAdd(dst + 0, f0.x * w);
        atomicAdd(dst + 1, f0.y * w);
        atomicAdd(dst + 2, f1.x * w);
        atomicAdd(dst + 3, f1.y * w);
    }
}

// ---------------------------------------------------------------- launch
extern "C" void kernel_launch(void* const* d_in, const int* in_sizes, int n_in,
                              void* d_out, int out_size)
{
    const float* x    = (const float*)d_in[0];
    const void*  ei   = d_in[1];
    const float* Wf   = (const float*)d_in[2];
    const float* Wb   = (const float*)d_in[3];
    const float* bias = (const float*)d_in[4];
    float*       y    = (float*)d_out;

    int M  = in_sizes[0] / DIN;
    int E2 = in_sizes[1];
    int E  = E2 / 2;

    static cudaStream_t s1 = nullptr, s2 = nullptr, s3 = nullptr;
    static cudaEvent_t ev_fork = nullptr, ev_zero = nullptr, ev_fill = nullptr,
                       ev_isr = nullptr, ev_gemm = nullptr, ev_gb = nullptr;
    static void *p_cnt_c = nullptr, *p_cnt_r = nullptr, *p_novf = nullptr;
    static bool tried = false;
    if (!tried) {
        tried = true;
        cudaFuncSetAttribute(gemm_hmma_kernel,
                             cudaFuncAttributeMaxDynamicSharedMemorySize, GEMM_SMEM);
        cudaGetSymbolAddress(&p_cnt_c, g_cnt_c);
        cudaGetSymbolAddress(&p_cnt_r, g_cnt_r);
        cudaGetSymbolAddress(&p_novf, g_novf);
        bool ok = (cudaStreamCreateWithFlags(&s1, cudaStreamNonBlocking) == cudaSuccess)
               && (cudaStreamCreateWithFlags(&s2, cudaStreamNonBlocking) == cudaSuccess)
               && (cudaStreamCreateWithFlags(&s3, cudaStreamNonBlocking) == cudaSuccess);
        if (ok) {
            cudaEventCreateWithFlags(&ev_fork, cudaEventDisableTiming);
            cudaEventCreateWithFlags(&ev_zero, cudaEventDisableTiming);
            cudaEventCreateWithFlags(&ev_fill, cudaEventDisableTiming);
            cudaEventCreateWithFlags(&ev_isr, cudaEventDisableTiming);
            cudaEventCreateWithFlags(&ev_gemm, cudaEventDisableTiming);
            cudaEventCreateWithFlags(&ev_gb, cudaEventDisableTiming);
        } else { s1 = s2 = s3 = nullptr; }
    }

    int eblocks = (E + 255) / 256;
    int gblocks = (M * 32 + 255) / 256;

    if (s1 && p_cnt_c && p_cnt_r && p_novf) {
        cudaEventRecord(ev_fork, 0);
        cudaStreamWaitEvent(s1, ev_fork, 0);
        cudaStreamWaitEvent(s2, ev_fork, 0);
        cudaStreamWaitEvent(s3, ev_fork, 0);

        // s2: zero counts + overflow counters (copy engine)
        cudaMemsetAsync(p_cnt_c, 0, (size_t)M * sizeof(int), s2);
        cudaMemsetAsync(p_cnt_r, 0, (size_t)M * sizeof(int), s2);
        cudaMemsetAsync(p_novf, 0, 2 * sizeof(int), s2);
        cudaEventRecord(ev_zero, s2);

        // s1: detect -> single-pass bucket build
        detect_flag_kernel<<<1, 1024, 0, s1>>>((const unsigned*)ei, E2);
        cudaStreamWaitEvent(s1, ev_zero, 0);
        fill_bucket_kernel<<<eblocks, 256, 0, s1>>>(ei, E);
        cudaEventRecord(ev_fill, s1);

        // s3: isr (needs final counts)
        cudaStreamWaitEvent(s3, ev_fill, 0);
        isr_kernel<<<(M + 255) / 256, 256, 0, s3>>>(M);
        cudaEventRecord(ev_isr, s3);

        // main: GEMM chain from t=0 (independent of graph)
        w_conv_kernel<<<256, 256>>>(Wf, Wb);
        gemm_hmma_kernel<<<(M + 63) / 64, 256, GEMM_SMEM>>>(x, M);
        cudaEventRecord(ev_gemm, 0);

        // gathers: fwd on main (after fill+isr; gemm in-order), bwd on s2
        cudaStreamWaitEvent(0, ev_fill, 0);
        cudaStreamWaitEvent(0, ev_isr, 0);
        gather_kernel<<<gblocks, 256, 0, 0>>>(0, bias, y, M);
        cudaStreamWaitEvent(s2, ev_fill, 0);
        cudaStreamWaitEvent(s2, ev_isr, 0);
        cudaStreamWaitEvent(s2, ev_gemm, 0);
        gather_kernel<<<gblocks, 256, 0, s2>>>(1, bias, y, M);
        cudaEventRecord(ev_gb, s2);

        // overflow replay after both gathers
        cudaStreamWaitEvent(0, ev_gb, 0);
        ovf_kernel<<<32, 256, 0, 0>>>(0, y);
        ovf_kernel<<<32, 256, 0, 0>>>(1, y);
    } else {
        cudaMemsetAsync(p_cnt_c, 0, (size_t)M * sizeof(int), 0);
        cudaMemsetAsync(p_cnt_r, 0, (size_t)M * sizeof(int), 0);
        cudaMemsetAsync(p_novf, 0, 2 * sizeof(int), 0);
        detect_flag_kernel<<<1, 1024>>>((const unsigned*)ei, E2);
        fill_bucket_kernel<<<eblocks, 256>>>(ei, E);
        isr_kernel<<<(M + 255) / 256, 256>>>(M);
        w_conv_kernel<<<256, 256>>>(Wf, Wb);
        gemm_hmma_kernel<<<(M + 63) / 64, 256, GEMM_SMEM>>>(x, M);
        gather_kernel<<<gblocks, 256>>>(0, bias, y, M);
        gather_kernel<<<gblocks, 256>>>(1, bias, y, M);
        ovf_kernel<<<32, 256>>>(0, y);
        ovf_kernel<<<32, 256>>>(1, y);
    }
}

// round 14
// speedup vs baseline: 1.2442x; 1.2442x over previous
#include <cuda_runtime.h>
#include <cuda_fp16.h>
#include <cstdint>
#include <cstddef>

#define NN_MAX 100000
#define NE_MAX 1600000
#define DIN 256
#define DH 128
#define CAP 64
#define OVF_MAX 8192

typedef unsigned long long ull;

// ---------------------------------------------------------------- scratch
__device__ __half g_xf[NN_MAX * DH];   // (x @ W_f^T)[n]  fp16, unscaled
__device__ __half g_xb[NN_MAX * DH];   // (x @ W_b^T)[n]  fp16, unscaled
__device__ __half g_wc[256 * DIN];     // W fp16 [n][k] (Wf rows 0-127, Wb 128-255)
__device__ int   g_cnt_c[NN_MAX];      // in-degree (edges only)
__device__ int   g_cnt_r[NN_MAX];      // out-degree (edges only)
__device__ float g_isr_in[NN_MAX];
__device__ float g_isr_out[NN_MAX];
__device__ int   g_bf[NN_MAX * CAP];   // fwd buckets: sources (rows) per col
__device__ int   g_bb[NN_MAX * CAP];   // bwd buckets: sources (cols) per row
__device__ int   g_novf[2];
__device__ int2  g_ovf_f[OVF_MAX];     // (dest c, src r)
__device__ int2  g_ovf_b[OVF_MAX];     // (dest r, src c)
__device__ int   g_is64;

__device__ __forceinline__ int edge_val(const void* ei, size_t idx) {
    if (g_is64) return (int)((const long long*)ei)[idx];
    return ((const int*)ei)[idx];
}

// ---------------------------------------------------------------- dtype detect
__global__ void detect_flag_kernel(const unsigned* __restrict__ w, int nwords) {
    __shared__ unsigned s;
    if (threadIdx.x == 0) s = 0;
    __syncthreads();
    unsigned acc = 0;
    for (int i = threadIdx.x; i < 16384 && 2 * i + 1 < nwords; i += blockDim.x)
        acc |= w[2 * i + 1];
    #pragma unroll
    for (int o = 16; o > 0; o >>= 1)
        acc |= __shfl_xor_sync(0xffffffffu, acc, o);
    if ((threadIdx.x & 31) == 0 && acc) atomicOr(&s, acc);
    __syncthreads();
    if (threadIdx.x == 0) g_is64 = (s == 0u) ? 1 : 0;
}

// ---------------------------------------------------------------- single-pass bucket CSR
__global__ void fill_bucket_kernel(const void* __restrict__ ei, int E) {
    int e = blockIdx.x * blockDim.x + threadIdx.x;
    if (e >= E) return;
    int c = edge_val(ei, e);
    int r = edge_val(ei, (size_t)E + e);
    int pc = atomicAdd(&g_cnt_c[c], 1);
    if (pc < CAP) g_bf[c * CAP + pc] = r;
    else {
        int o = atomicAdd(&g_novf[0], 1);
        if (o < OVF_MAX) g_ovf_f[o] = make_int2(c, r);
    }
    int pr = atomicAdd(&g_cnt_r[r], 1);
    if (pr < CAP) g_bb[r * CAP + pr] = c;
    else {
        int o = atomicAdd(&g_novf[1], 1);
        if (o < OVF_MAX) g_ovf_b[o] = make_int2(r, c);
    }
}

__global__ void isr_kernel(int M) {
    int n = blockIdx.x * blockDim.x + threadIdx.x;
    if (n >= M) return;
    g_isr_in[n]  = rsqrtf((float)(g_cnt_c[n] + 1));
    g_isr_out[n] = rsqrtf((float)(g_cnt_r[n] + 1));
}

// ---------------------------------------------------------------- W prep (fp16)
__global__ void w_conv_kernel(const float* __restrict__ Wf,
                              const float* __restrict__ Wb) {
    int idx = blockIdx.x * blockDim.x + threadIdx.x;
    if (idx >= 256 * 256) return;
    int n = idx >> 8, k = idx & 255;
    float v = (n < DH) ? Wf[n * DIN + k] : Wb[(n - DH) * DIN + k];
    g_wc[n * DIN + k] = __float2half_rn(v);
}

// ---------------------------------------------------------------- HMMA GEMM (reads x fp32 directly)
#define LDA 72
#define LDB 72
#define A_BUF (64 * LDA)
#define B_BUF (256 * LDB)
#define GEMM_SMEM ((2 * A_BUF + 2 * B_BUF) * 2)
#define NCHUNK 4

__device__ __forceinline__ void cp16(unsigned daddr, const void* src, unsigned sz) {
    asm volatile("cp.async.ca.shared.global [%0], [%1], 16, %2;"
                 :: "r"(daddr), "l"(src), "r"(sz) : "memory");
}

__global__ __launch_bounds__(256)
void gemm_hmma_kernel(const float* __restrict__ x, int M)
{
    extern __shared__ __align__(16) __half smem[];
    __half* As = smem;
    __half* Bs = smem + 2 * A_BUF;

    const int t   = threadIdx.x;
    const int wid = t >> 5;
    const int lid = t & 31;
    const int m0  = blockIdx.x * 64;
    const int wm  = (wid & 1) * 32;
    const int wn  = (wid >> 1) * 64;

    float c[2][8][4];
    #pragma unroll
    for (int i = 0; i < 2; ++i)
        #pragma unroll
        for (int j = 0; j < 8; ++j)
            #pragma unroll
            for (int q = 0; q < 4; ++q) c[i][j][q] = 0.f;

    unsigned bs_base = (unsigned)__cvta_generic_to_shared(Bs);

    auto issue_load = [&](int ch) {
        int buf = ch & 1;
        int k0 = ch * 64;
        #pragma unroll
        for (int i = 0; i < 8; ++i) {
            int idx = t + 256 * i;
            int row = idx >> 3, kq = idx & 7;
            const __half* src = g_wc + (size_t)row * DIN + k0 + kq * 8;
            unsigned dst = bs_base + (buf * B_BUF + row * LDB + kq * 8) * 2;
            cp16(dst, src, 16u);
        }
        asm volatile("cp.async.commit_group;" ::: "memory");
        #pragma unroll
        for (int i = 0; i < 2; ++i) {
            int idx = t + 256 * i;
            int row = idx >> 3, kq = idx & 7;
            float4 f0 = make_float4(0.f, 0.f, 0.f, 0.f), f1 = f0;
            if (m0 + row < M) {
                const float* src = x + (size_t)(m0 + row) * DIN + k0 + kq * 8;
                f0 = *(const float4*)src;
                f1 = *(const float4*)(src + 4);
            }
            __half2 h0 = __floats2half2_rn(f0.x, f0.y);
            __half2 h1 = __floats2half2_rn(f0.z, f0.w);
            __half2 h2 = __floats2half2_rn(f1.x, f1.y);
            __half2 h3 = __floats2half2_rn(f1.z, f1.w);
            uint4 u = make_uint4(*(unsigned*)&h0, *(unsigned*)&h1,
                                 *(unsigned*)&h2, *(unsigned*)&h3);
            *(uint4*)(As + buf * A_BUF + row * LDA + kq * 8) = u;
        }
    };

    issue_load(0);
    issue_load(1);

    #pragma unroll 1
    for (int ch = 0; ch < NCHUNK; ++ch) {
        if (ch == NCHUNK - 1) asm volatile("cp.async.wait_group 0;" ::: "memory");
        else                  asm volatile("cp.async.wait_group 1;" ::: "memory");
        __syncthreads();

        const __half* A_ = As + (ch & 1) * A_BUF;
        const __half* B_ = Bs + (ch & 1) * B_BUF;

        #pragma unroll
        for (int k16 = 0; k16 < 4; ++k16) {
            int k0 = k16 * 16 + (lid & 3) * 2;
            unsigned a[2][4];
            #pragma unroll
            for (int mt = 0; mt < 2; ++mt) {
                int r = wm + mt * 16 + (lid >> 2);
                a[mt][0] = *(const unsigned*)(A_ + r * LDA + k0);
                a[mt][1] = *(const unsigned*)(A_ + (r + 8) * LDA + k0);
                a[mt][2] = *(const unsigned*)(A_ + r * LDA + k0 + 8);
                a[mt][3] = *(const unsigned*)(A_ + (r + 8) * LDA + k0 + 8);
            }
            #pragma unroll
            for (int nt = 0; nt < 8; ++nt) {
                int nrow = wn + nt * 8 + (lid >> 2);
                unsigned b0 = *(const unsigned*)(B_ + nrow * LDB + k0);
                unsigned b1 = *(const unsigned*)(B_ + nrow * LDB + k0 + 8);
                #pragma unroll
                for (int mt = 0; mt < 2; ++mt) {
                    asm volatile(
                        "mma.sync.aligned.m16n8k16.row.col.f32.f16.f16.f32 "
                        "{%0,%1,%2,%3}, {%4,%5,%6,%7}, {%8,%9}, {%0,%1,%2,%3};"
                        : "+f"(c[mt][nt][0]), "+f"(c[mt][nt][1]),
                          "+f"(c[mt][nt][2]), "+f"(c[mt][nt][3])
                        : "r"(a[mt][0]), "r"(a[mt][1]), "r"(a[mt][2]), "r"(a[mt][3]),
                          "r"(b0), "r"(b1));
                }
            }
        }
        __syncthreads();
        if (ch + 2 < NCHUNK) issue_load(ch + 2);
    }

    #pragma unroll
    for (int mt = 0; mt < 2; ++mt) {
        #pragma unroll
        for (int half2s = 0; half2s < 2; ++half2s) {
            int node = m0 + wm + mt * 16 + (lid >> 2) + half2s * 8;
            if (node >= M) continue;
            #pragma unroll
            for (int nt = 0; nt < 8; ++nt) {
                int n = wn + nt * 8 + (lid & 3) * 2;
                __half2 h = __floats2half2_rn(c[mt][nt][half2s * 2],
                                              c[mt][nt][half2s * 2 + 1]);
                __half* dst = (n < DH) ? (g_xf + (size_t)node * DH + n)
                                       : (g_xb + (size_t)node * DH + (n - DH));
                *(__half2*)dst = h;
            }
        }
    }
}

// ---------------------------------------------------------------- gather (fused fwd+bwd, grid.y = sel)
// Warp per node; lane = 4 consecutive cols (uint2). MLP-4 batches (proven loop).
__global__ __launch_bounds__(256)
void gather_kernel(const float* __restrict__ bias,
                   float* __restrict__ y, int M)
{
    int sel  = blockIdx.y;
    int lane = threadIdx.x & 31;
    int n = (blockIdx.x * blockDim.x + threadIdx.x) >> 5;
    if (n >= M) return;

    const int* elist   = sel ? g_bb : g_bf;
    const int* cnt     = sel ? g_cnt_r : g_cnt_c;
    const __half* feat = sel ? g_xb : g_xf;
    const float* sarr  = sel ? g_isr_in : g_isr_out;
    float nscale = sel ? g_isr_out[n] : g_isr_in[n];
    int ycol0 = sel ? 32 : 0;

    int beg = n * CAP;
    int deg = min(cnt[n], CAP);

    float4 acc;
    {   // self term
        float ws = sarr[n];
        uint2 rv = *(const uint2*)(feat + (size_t)n * DH + lane * 4);
        float2 f0 = __half22float2(*(__half2*)&rv.x);
        float2 f1 = __half22float2(*(__half2*)&rv.y);
        acc = make_float4(f0.x * ws, f0.y * ws, f1.x * ws, f1.y * ws);
    }

    for (int base = 0; base < deg; base += 32) {
        int e = base + lane;
        int src = 0; float w = 0.f;
        if (e < deg) {
            src = __ldg(elist + beg + e);
            w   = __ldg(sarr + src);
        }
        int m = min(32, deg - base);
        int j = 0;
        for (; j + 4 <= m; j += 4) {
            int s0 = __shfl_sync(0xffffffffu, src, j);
            int s1 = __shfl_sync(0xffffffffu, src, j + 1);
            int s2 = __shfl_sync(0xffffffffu, src, j + 2);
            int s3 = __shfl_sync(0xffffffffu, src, j + 3);
            float w0 = __shfl_sync(0xffffffffu, w, j);
            float w1 = __shfl_sync(0xffffffffu, w, j + 1);
            float w2 = __shfl_sync(0xffffffffu, w, j + 2);
            float w3 = __shfl_sync(0xffffffffu, w, j + 3);
            uint2 v0 = __ldg((const uint2*)(feat + (size_t)s0 * DH) + lane);
            uint2 v1 = __ldg((const uint2*)(feat + (size_t)s1 * DH) + lane);
            uint2 v2 = __ldg((const uint2*)(feat + (size_t)s2 * DH) + lane);
            uint2 v3 = __ldg((const uint2*)(feat + (size_t)s3 * DH) + lane);
            float2 a0, a1;
            a0 = __half22float2(*(__half2*)&v0.x); a1 = __half22float2(*(__half2*)&v0.y);
            acc.x += a0.x * w0; acc.y += a0.y * w0; acc.z += a1.x * w0; acc.w += a1.y * w0;
            a0 = __half22float2(*(__half2*)&v1.x); a1 = __half22float2(*(__half2*)&v1.y);
            acc.x += a0.x * w1; acc.y += a0.y * w1; acc.z += a1.x * w1; acc.w += a1.y * w1;
            a0 = __half22float2(*(__half2*)&v2.x); a1 = __half22float2(*(__half2*)&v2.y);
            acc.x += a0.x * w2; acc.y += a0.y * w2; acc.z += a1.x * w2; acc.w += a1.y * w2;
            a0 = __half22float2(*(__half2*)&v3.x); a1 = __half22float2(*(__half2*)&v3.y);
            acc.x += a0.x * w3; acc.y += a0.y * w3; acc.z += a1.x * w3; acc.w += a1.y * w3;
        }
        for (; j < m; ++j) {
            int s0 = __shfl_sync(0xffffffffu, src, j);
            float w0 = __shfl_sync(0xffffffffu, w, j);
            uint2 v0 = __ldg((const uint2*)(feat + (size_t)s0 * DH) + lane);
            float2 a0 = __half22float2(*(__half2*)&v0.x);
            float2 a1 = __half22float2(*(__half2*)&v0.y);
            acc.x += a0.x * w0; acc.y += a0.y * w0; acc.z += a1.x * w0; acc.w += a1.y * w0;
        }
    }

    float4 b = ((const float4*)(bias + sel * DH))[lane];
    float4 o = make_float4(b.x + nscale * acc.x, b.y + nscale * acc.y,
                           b.z + nscale * acc.z, b.w + nscale * acc.w);
    ((float4*)y)[(size_t)n * 64 + ycol0 + lane] = o;
}

// ---------------------------------------------------------------- overflow replay (normally empty)
__global__ void ovf_kernel(float* __restrict__ y) {
    int sel = blockIdx.y;
    int n_ovf = min(g_novf[sel], OVF_MAX);
    if (n_ovf <= 0) return;
    const int2* lst = sel ? g_ovf_b : g_ovf_f;
    const __half* feat = sel ? g_xb : g_xf;
    int lane = threadIdx.x & 31;
    int wpg = (gridDim.x * blockDim.x) >> 5;
    for (int i = (blockIdx.x * blockDim.x + threadIdx.x) >> 5; i < n_ovf; i += wpg) {
        int2 p = lst[i];   // (dest, src)
        float w = sel ? (g_isr_out[p.x] * g_isr_in[p.y])
                      : (g_isr_in[p.x] * g_isr_out[p.y]);
        uint2 v = *(const uint2*)(feat + (size_t)p.y * DH + lane * 4);
        float2 f0 = __half22float2(*(__half2*)&v.x);
        float2 f1 = __half22float2(*(__half2*)&v.y);
        float* dst = y + (size_t)p.x * 256 + sel * DH + lane * 4;
        atomicAdd(dst + 0, f0.x * w);
        atomicAdd(dst + 1, f0.y * w);
        atomicAdd(dst + 2, f1.x * w);
        atomicAdd(dst + 3, f1.y * w);
    }
}

// ---------------------------------------------------------------- launch
extern "C" void kernel_launch(void* const* d_in, const int* in_sizes, int n_in,
                              void* d_out, int out_size)
{
    const float* x    = (const float*)d_in[0];
    const void*  ei   = d_in[1];
    const float* Wf   = (const float*)d_in[2];
    const float* Wb   = (const float*)d_in[3];
    const float* bias = (const float*)d_in[4];
    float*       y    = (float*)d_out;

    int M  = in_sizes[0] / DIN;
    int E2 = in_sizes[1];
    int E  = E2 / 2;

    static cudaStream_t s1 = nullptr, s2 = nullptr, s3 = nullptr;
    static cudaEvent_t ev_fork = nullptr, ev_zero = nullptr, ev_fill = nullptr,
                       ev_isr = nullptr;
    static void *p_cnt_c = nullptr, *p_cnt_r = nullptr, *p_novf = nullptr;
    static bool tried = false;
    if (!tried) {
        tried = true;
        cudaFuncSetAttribute(gemm_hmma_kernel,
                             cudaFuncAttributeMaxDynamicSharedMemorySize, GEMM_SMEM);
        cudaGetSymbolAddress(&p_cnt_c, g_cnt_c);
        cudaGetSymbolAddress(&p_cnt_r, g_cnt_r);
        cudaGetSymbolAddress(&p_novf, g_novf);
        bool ok = (cudaStreamCreateWithFlags(&s1, cudaStreamNonBlocking) == cudaSuccess)
               && (cudaStreamCreateWithFlags(&s2, cudaStreamNonBlocking) == cudaSuccess)
               && (cudaStreamCreateWithFlags(&s3, cudaStreamNonBlocking) == cudaSuccess);
        if (ok) {
            cudaEventCreateWithFlags(&ev_fork, cudaEventDisableTiming);
            cudaEventCreateWithFlags(&ev_zero, cudaEventDisableTiming);
            cudaEventCreateWithFlags(&ev_fill, cudaEventDisableTiming);
            cudaEventCreateWithFlags(&ev_isr, cudaEventDisableTiming);
        } else { s1 = s2 = s3 = nullptr; }
    }

    int eblocks = (E + 255) / 256;
    dim3 ggrid((M * 32 + 255) / 256, 2);
    dim3 ogrid(32, 2);

    if (s1 && p_cnt_c && p_cnt_r && p_novf) {
        cudaEventRecord(ev_fork, 0);
        cudaStreamWaitEvent(s1, ev_fork, 0);
        cudaStreamWaitEvent(s2, ev_fork, 0);
        cudaStreamWaitEvent(s3, ev_fork, 0);

        // s2: zero counts + overflow counters (copy engine)
        cudaMemsetAsync(p_cnt_c, 0, (size_t)M * sizeof(int), s2);
        cudaMemsetAsync(p_cnt_r, 0, (size_t)M * sizeof(int), s2);
        cudaMemsetAsync(p_novf, 0, 2 * sizeof(int), s2);
        cudaEventRecord(ev_zero, s2);

        // s1: detect -> single-pass bucket build
        detect_flag_kernel<<<1, 1024, 0, s1>>>((const unsigned*)ei, E2);
        cudaStreamWaitEvent(s1, ev_zero, 0);
        fill_bucket_kernel<<<eblocks, 256, 0, s1>>>(ei, E);
        cudaEventRecord(ev_fill, s1);

        // s3: isr (needs final counts)
        cudaStreamWaitEvent(s3, ev_fill, 0);
        isr_kernel<<<(M + 255) / 256, 256, 0, s3>>>(M);
        cudaEventRecord(ev_isr, s3);

        // main: GEMM chain from t=0 (independent of graph)
        w_conv_kernel<<<256, 256>>>(Wf, Wb);
        gemm_hmma_kernel<<<(M + 63) / 64, 256, GEMM_SMEM>>>(x, M);

        // fused gather (both directions, one launch) after fill+isr (gemm in-order)
        cudaStreamWaitEvent(0, ev_fill, 0);
        cudaStreamWaitEvent(0, ev_isr, 0);
        gather_kernel<<<ggrid, 256, 0, 0>>>(bias, y, M);

        // overflow replay inline (normally empty)
        ovf_kernel<<<ogrid, 256, 0, 0>>>(y);
    } else {
        cudaMemsetAsync(p_cnt_c, 0, (size_t)M * sizeof(int), 0);
        cudaMemsetAsync(p_cnt_r, 0, (size_t)M * sizeof(int), 0);
        cudaMemsetAsync(p_novf, 0, 2 * sizeof(int), 0);
        detect_flag_kernel<<<1, 1024>>>((const unsigned*)ei, E2);
        fill_bucket_kernel<<<eblocks, 256>>>(ei, E);
        isr_kernel<<<(M + 255) / 256, 256>>>(M);
        w_conv_kernel<<<256, 256>>>(Wf, Wb);
        gemm_hmma_kernel<<<(M + 63) / 64, 256, GEMM_SMEM>>>(x, M);
        gather_kernel<<<ggrid, 256>>>(bias, y, M);
        ovf_kernel<<<ogrid, 256>>>(y);
    }
}